// round 15
// baseline (speedup 1.0000x reference)
#include <cuda_runtime.h>
#include <cuda_fp16.h>
#include <cstdint>

// Problem constants
#define Bb 4
#define Cc 64
#define Dd 8
#define Nn 4096          // H*W
#define LOG2E 1.4426950408889634f
#define TK 128           // keys per tile
#define NQ 128           // queries per CTA
#define KS 4             // key splits
#define NTS (Nn / TK / KS)   // 8 tiles per CTA

// Scratch (allocation-free rule: __device__ globals) — all row-major [row][n] f16
__device__ __half g_qh[Bb * Dd * Nn];                // [b][d][n] f16 (q, scaled by log2e)
__device__ __half g_kh[Bb * Dd * Nn];                // [b][d][n] f16
__device__ __half g_vh[Bb * Cc * Nn];                // [b][c][n] f16
__device__ __half g_po[Bb * KS * Cc * Nn];           // partial O (unnormalized, f16)
__device__ float  g_pl[Bb * KS * Nn];                // partial l

// ---------------- PTX helpers (baseline ISA only) ----------------
__device__ __forceinline__ uint32_t smem_u32(const void* p) {
    uint32_t a;
    asm("{ .reg .u64 t; cvta.to.shared.u64 t, %1; cvt.u32.u64 %0, t; }" : "=r"(a) : "l"(p));
    return a;
}
// d = {lo, hi} f16x2 (lo in low half)
__device__ __forceinline__ uint32_t cvtf16x2(float lo, float hi) {
    uint32_t r;
    asm("cvt.rn.f16x2.f32 %0, %1, %2;" : "=r"(r) : "f"(hi), "f"(lo));
    return r;
}
__device__ __forceinline__ uint32_t ex2h2(uint32_t a) {
    uint32_t r;
    asm("ex2.approx.f16x2 %0, %1;" : "=r"(r) : "r"(a));
    return r;
}
__device__ __forceinline__ void ldsm4(uint32_t& r0, uint32_t& r1, uint32_t& r2,
                                      uint32_t& r3, uint32_t a) {
    asm volatile("ldmatrix.sync.aligned.m8n8.x4.shared.b16 {%0, %1, %2, %3}, [%4];"
                 : "=r"(r0), "=r"(r1), "=r"(r2), "=r"(r3) : "r"(a));
}
__device__ __forceinline__ void ldsm4t(uint32_t& r0, uint32_t& r1, uint32_t& r2,
                                       uint32_t& r3, uint32_t a) {
    asm volatile("ldmatrix.sync.aligned.m8n8.x4.trans.shared.b16 {%0, %1, %2, %3}, [%4];"
                 : "=r"(r0), "=r"(r1), "=r"(r2), "=r"(r3) : "r"(a));
}
__device__ __forceinline__ void ldsm2t(uint32_t& r0, uint32_t& r1, uint32_t a) {
    asm volatile("ldmatrix.sync.aligned.m8n8.x2.trans.shared.b16 {%0, %1}, [%2];"
                 : "=r"(r0), "=r"(r1) : "r"(a));
}
__device__ __forceinline__ void sts32(uint32_t a, uint32_t v) {
    asm volatile("st.shared.b32 [%0], %1;" :: "r"(a), "r"(v) : "memory");
}
__device__ __forceinline__ void sts_v2b32(uint32_t a, uint32_t x, uint32_t y) {
    asm volatile("st.shared.v2.b32 [%0], {%1, %2};" :: "r"(a), "r"(x), "r"(y) : "memory");
}
__device__ __forceinline__ void lds128(uint32_t a, uint32_t& x, uint32_t& y,
                                       uint32_t& z, uint32_t& w) {
    asm volatile("ld.shared.v4.b32 {%0, %1, %2, %3}, [%4];"
                 : "=r"(x), "=r"(y), "=r"(z), "=r"(w) : "r"(a));
}
__device__ __forceinline__ void cp16(uint32_t dst, const void* src) {
    asm volatile("cp.async.ca.shared.global [%0], [%1], 16;" :: "r"(dst), "l"(src) : "memory");
}
#define CP_COMMIT() asm volatile("cp.async.commit_group;" ::: "memory")
#define CP_WAIT1()  asm volatile("cp.async.wait_group 1;" ::: "memory")
#define CP_WAIT0()  asm volatile("cp.async.wait_group 0;" ::: "memory")

// S[16q x 8k] = Q[16x8] * K^T, f16 accumulate from zero -> packed f16x2 D
__device__ __forceinline__ void mma_qk8h(uint32_t d[2], uint32_t a0, uint32_t a1,
                                         uint32_t b0) {
    const uint32_t Z = 0;
    asm volatile(
        "mma.sync.aligned.m16n8k8.row.col.f16.f16.f16.f16 "
        "{%0,%1}, {%2,%3}, {%4}, {%5,%5};"
        : "=r"(d[0]), "=r"(d[1])
        : "r"(a0), "r"(a1), "r"(b0), "r"(Z));
}
// PV: f16 accumulate in-place (2x rate vs f32 accum on legacy mma path)
__device__ __forceinline__ void mma_pv16h(uint32_t d[2], uint32_t a0, uint32_t a1,
                                          uint32_t a2, uint32_t a3,
                                          uint32_t b0, uint32_t b1) {
    asm volatile(
        "mma.sync.aligned.m16n8k16.row.col.f16.f16.f16.f16 "
        "{%0,%1}, {%2,%3,%4,%5}, {%6,%7}, {%0,%1};"
        : "+r"(d[0]), "+r"(d[1])
        : "r"(a0), "r"(a1), "r"(a2), "r"(a3), "r"(b0), "r"(b1));
}
__device__ __forceinline__ void mma16816(float d[4], uint32_t a0, uint32_t a1,
                                         uint32_t a2, uint32_t a3,
                                         uint32_t b0, uint32_t b1) {
    asm volatile(
        "mma.sync.aligned.m16n8k16.row.col.f32.f16.f16.f32 "
        "{%0,%1,%2,%3}, {%4,%5,%6,%7}, {%8,%9}, {%0,%1,%2,%3};"
        : "+f"(d[0]), "+f"(d[1]), "+f"(d[2]), "+f"(d[3])
        : "r"(a0), "r"(a1), "r"(a2), "r"(a3), "r"(b0), "r"(b1));
}

// ============================================================
// Kernel 1: fused 1x1-conv QKV projection on HMMA (round-12).
// grid (Nn/128, Bb), 256 threads
// ============================================================
__global__ void __launch_bounds__(256) qkv_kernel(
    const float* __restrict__ x,
    const float* __restrict__ Wq, const float* __restrict__ bq,
    const float* __restrict__ Wk, const float* __restrict__ bk,
    const float* __restrict__ Wv, const float* __restrict__ bv)
{
    __shared__ __align__(16) char smem[28928];   // WH 11520 | XH 17408 ; TR reuses [0,21760)
    const uint32_t sb = smem_u32(smem);
    const uint32_t WH = sb;
    const uint32_t XH = sb + 11520;
    const uint32_t TR = sb;

    const int tid  = threadIdx.x;
    const int w    = tid >> 5;
    const int lane = tid & 31;
    const int gid  = lane >> 2;
    const int tg   = lane & 3;
    const int b    = blockIdx.y;
    const int n0   = blockIdx.x * 128;

    // ---- convert stacked W -> f16 smem (rows 144B) ----
#pragma unroll
    for (int i = 0; i < 10; i++) {
        const int flat = (tid + i * 256) * 2;      // even f32 index in 80x64
        const int o = flat >> 6, c = flat & 63;
        const float* src = (o < 64) ? Wv + o * 64 + c
                         : (o < 72) ? Wq + (o - 64) * 64 + c
                                    : Wk + (o - 72) * 64 + c;
        const float2 v = *(const float2*)src;
        const float scl = (o >= 64 && o < 72) ? LOG2E : 1.0f;
        sts32(WH + (uint32_t)(o * 144 + c * 2), cvtf16x2(v.x * scl, v.y * scl));
    }
    // ---- convert x tile -> f16 smem [c][px] (rows 272B) ----
#pragma unroll
    for (int i = 0; i < 8; i++) {
        const int id = tid + i * 256;
        const int c = id >> 5, ch = id & 31;
        const float4 v = *(const float4*)&x[(size_t)(b * Cc + c) * Nn + n0 + ch * 4];
        sts_v2b32(XH + (uint32_t)(c * 272 + ch * 8),
                  cvtf16x2(v.x, v.y), cvtf16x2(v.z, v.w));
    }
    // ---- per-thread biases (rt<4: V rows; rt=4: Q(gid)/K(gid)) ----
    float bias[5][2];
#pragma unroll
    for (int rt = 0; rt < 4; rt++) {
        bias[rt][0] = bv[rt * 16 + gid];
        bias[rt][1] = bv[rt * 16 + gid + 8];
    }
    bias[4][0] = bq[gid] * LOG2E;
    bias[4][1] = bk[gid];

    __syncthreads();

    // ---- GEMM ----
    float acc[5][2][4];
#pragma unroll
    for (int rt = 0; rt < 5; rt++)
#pragma unroll
        for (int nt = 0; nt < 2; nt++)
#pragma unroll
            for (int i = 0; i < 4; i++) acc[rt][nt][i] = 0.f;

    const int wpx = w * 16;
    const uint32_t aoff = WH + (uint32_t)((lane & 15) * 144 + (lane >> 4) * 16);
    const int q2 = lane >> 3;
    const uint32_t boff = XH + (uint32_t)(((q2 & 1) * 8 + (lane & 7)) * 272
                                          + (wpx + (q2 >> 1) * 8) * 2);
#pragma unroll
    for (int ks = 0; ks < 4; ks++) {
        uint32_t b0, b1, b2, b3;
        ldsm4t(b0, b1, b2, b3, boff + (uint32_t)(ks * 16 * 272));
#pragma unroll
        for (int rt = 0; rt < 5; rt++) {
            uint32_t a0, a1, a2, a3;
            ldsm4(a0, a1, a2, a3, aoff + (uint32_t)(rt * 16 * 144 + ks * 32));
            mma16816(acc[rt][0], a0, a1, a2, a3, b0, b1);
            mma16816(acc[rt][1], a0, a1, a2, a3, b2, b3);
        }
    }
    __syncthreads();

    // ---- transpose tile [o][px] f16 (rows 272B) ----
#pragma unroll
    for (int rt = 0; rt < 5; rt++)
#pragma unroll
        for (int nt = 0; nt < 2; nt++) {
            const int px = wpx + nt * 8 + tg * 2;
            const int o0 = rt * 16 + gid;
            sts32(TR + (uint32_t)(o0 * 272 + px * 2),
                  cvtf16x2(acc[rt][nt][0] + bias[rt][0],
                           acc[rt][nt][1] + bias[rt][0]));
            sts32(TR + (uint32_t)((o0 + 8) * 272 + px * 2),
                  cvtf16x2(acc[rt][nt][2] + bias[rt][1],
                           acc[rt][nt][3] + bias[rt][1]));
        }
    __syncthreads();

    // ---- coalesced stores ----
#pragma unroll
    for (int i = 0; i < 4; i++) {
        const int id = tid + i * 256;
        const int o = id >> 4, kc = id & 15;
        uint32_t v0, v1, v2, v3;
        lds128(TR + (uint32_t)(o * 272 + kc * 16), v0, v1, v2, v3);
        uint4* dst = (uint4*)&g_vh[(size_t)(b * Cc + o) * Nn + n0 + kc * 8];
        *dst = make_uint4(v0, v1, v2, v3);
    }
    {
        const int d16 = tid >> 4, kc = tid & 15;
        uint32_t v0, v1, v2, v3;
        lds128(TR + (uint32_t)((64 + d16) * 272 + kc * 16), v0, v1, v2, v3);
        __half* base = (d16 < 8) ? &g_qh[(size_t)(b * Dd + d16) * Nn]
                                 : &g_kh[(size_t)(b * Dd + d16 - 8) * Nn];
        *(uint4*)&base[n0 + kc * 8] = make_uint4(v0, v1, v2, v3);
    }
}

// ============================================================
// Kernel 2: attention — 128 threads / 4 warps, 32 queries per warp.
//   QK f16-accum mma; PV f16-accum mma (2x tensor rate);
//   l via f32-accum mma (precision anchor).
//   K tile [8d][128key] f16 (272B rows) -> ldmatrix.x2.trans
//   V tile [64c][128key] f16 (272B rows) -> ldmatrix.x4
//   Partial O stored f16. grid (32, KS=4, Bb) = 512 CTAs.
// ============================================================
__global__ void __launch_bounds__(128) attn_kernel()
{
    // 2 bufs x (2176B K + 17408B V) = 39168; epilogue sD 64x132 f32 = 33792
    __shared__ __align__(16) char smem[39168];
    const uint32_t sb = smem_u32(smem);

    const int tid  = threadIdx.x;
    const int w    = tid >> 5;
    const int lane = tid & 31;
    const int gid  = lane >> 2;   // 0..7
    const int tg   = lane & 3;    // 0..3
    const int b    = blockIdx.z;
    const int s    = blockIdx.y;
    const int row0 = blockIdx.x * NQ;
    const int key0 = s * (Nn / KS);
    const int rbase = row0 + w * 32 + gid;

    // ---- Q A-frags for two 16-row sets ----
    uint32_t qA0, qA1, qB0, qB1;
    {
        const size_t qb = (size_t)b * Dd * Nn;
        const __half* q0 = &g_qh[qb + (size_t)(2 * tg) * Nn];
        const __half* q1 = &g_qh[qb + (size_t)(2 * tg + 1) * Nn];
        qA0 = (uint32_t)*(const unsigned short*)&q0[rbase]
            | ((uint32_t)*(const unsigned short*)&q1[rbase] << 16);
        qA1 = (uint32_t)*(const unsigned short*)&q0[rbase + 8]
            | ((uint32_t)*(const unsigned short*)&q1[rbase + 8] << 16);
        qB0 = (uint32_t)*(const unsigned short*)&q0[rbase + 16]
            | ((uint32_t)*(const unsigned short*)&q1[rbase + 16] << 16);
        qB1 = (uint32_t)*(const unsigned short*)&q0[rbase + 24]
            | ((uint32_t)*(const unsigned short*)&q1[rbase + 24] << 16);
    }

    // ---- loop-constant ldmatrix lane offsets ----
    const int l16 = lane & 15;
    const uint32_t kmoff = (uint32_t)((l16 & 7) * 272 + (l16 >> 3) * 16);
    const int q2 = lane >> 3;
    uint32_t vmoff[4];
#pragma unroll
    for (int g = 0; g < 4; g++)
        vmoff[g] = (uint32_t)((g * 16 + (q2 >> 1) * 8 + (lane & 7)) * 272
                              + (q2 & 1) * 16);

    // f16 accumulators: [nt][2] packed f16x2
    uint32_t hacA[8][2], hacB[8][2];
#pragma unroll
    for (int nt = 0; nt < 8; nt++) {
        hacA[nt][0] = 0u; hacA[nt][1] = 0u;
        hacB[nt][0] = 0u; hacB[nt][1] = 0u;
    }
    float dlA[4] = {0.f, 0.f, 0.f, 0.f};
    float dlB[4] = {0.f, 0.f, 0.f, 0.f};
    const uint32_t ONES = 0x3C003C00u;

    auto prefetch = [&](int t, int buf) {
        const uint32_t kdst = sb + (uint32_t)buf * 19584u;
        const uint32_t vdst = kdst + 2176u;
        {
            const int d = tid >> 4, kc = tid & 15;
            cp16(kdst + (uint32_t)(d * 272 + kc * 16),
                 &g_kh[(size_t)(b * Dd + d) * Nn + key0 + t * TK + kc * 8]);
        }
#pragma unroll
        for (int j = 0; j < 8; j++) {
            const int id = tid + 128 * j;
            const int c = id >> 4, kc = id & 15;
            cp16(vdst + (uint32_t)(c * 272 + kc * 16),
                 &g_vh[(size_t)(b * Cc + c) * Nn + key0 + t * TK + kc * 8]);
        }
    };

    prefetch(0, 0);
    CP_COMMIT();

#pragma unroll 1
    for (int t = 0; t < NTS; t++) {
        if (t + 1 < NTS) { prefetch(t + 1, (t + 1) & 1); CP_COMMIT(); CP_WAIT1(); }
        else             { CP_WAIT0(); }
        __syncthreads();

        const uint32_t Kb = sb + (uint32_t)(t & 1) * 19584u;
        const uint32_t Vb = Kb + 2176u;

#pragma unroll
        for (int ks = 0; ks < 8; ks++) {
            uint32_t kb0, kb1;
            ldsm2t(kb0, kb1, Kb + (uint32_t)(ks * 32) + kmoff);
            // f16-accum QK: D regs are packed f16x2 in PV A-frag layout
            uint32_t sA0[2], sA1[2], sB0[2], sB1[2];
            mma_qk8h(sA0, qA0, qA1, kb0);
            mma_qk8h(sA1, qA0, qA1, kb1);
            mma_qk8h(sB0, qB0, qB1, kb0);
            mma_qk8h(sB1, qB0, qB1, kb1);

            const uint32_t a0 = ex2h2(sA0[0]);
            const uint32_t a1 = ex2h2(sA0[1]);
            const uint32_t a2 = ex2h2(sA1[0]);
            const uint32_t a3 = ex2h2(sA1[1]);
            const uint32_t a4 = ex2h2(sB0[0]);
            const uint32_t a5 = ex2h2(sB0[1]);
            const uint32_t a6 = ex2h2(sB1[0]);
            const uint32_t a7 = ex2h2(sB1[1]);

            const uint32_t vstep = Vb + (uint32_t)(ks * 32);
#pragma unroll
            for (int g = 0; g < 4; g++) {
                uint32_t r0, r1, r2, r3;
                ldsm4(r0, r1, r2, r3, vstep + vmoff[g]);
                mma_pv16h(hacA[2 * g],     a0, a1, a2, a3, r0, r1);
                mma_pv16h(hacB[2 * g],     a4, a5, a6, a7, r0, r1);
                mma_pv16h(hacA[2 * g + 1], a0, a1, a2, a3, r2, r3);
                mma_pv16h(hacB[2 * g + 1], a4, a5, a6, a7, r2, r3);
            }
            mma16816(dlA, a0, a1, a2, a3, ONES, ONES);
            mma16816(dlB, a4, a5, a6, a7, ONES, ONES);
        }
        __syncthreads();
    }

    // ---- partial l (rows rbase+{0,8,16,24}) ----
    if (tg == 0) {
        const size_t lb = ((size_t)(b * KS + s)) * Nn + rbase;
        g_pl[lb]      = dlA[0];
        g_pl[lb + 8]  = dlA[2];
        g_pl[lb + 16] = dlB[0];
        g_pl[lb + 24] = dlB[2];
    }

    // ---- transpose unnormalized O through smem (stride 132) ----
    float* sD = (float*)smem;
    {
        const int r = w * 32 + gid;
#pragma unroll
        for (int nt = 0; nt < 8; nt++) {
            const int c = nt * 8 + tg * 2;
            const float2 A0 = __half22float2(*(const __half2*)&hacA[nt][0]);
            const float2 A1 = __half22float2(*(const __half2*)&hacA[nt][1]);
            const float2 B0 = __half22float2(*(const __half2*)&hacB[nt][0]);
            const float2 B1 = __half22float2(*(const __half2*)&hacB[nt][1]);
            sD[c * 132 + r]            = A0.x;
            sD[(c + 1) * 132 + r]      = A0.y;
            sD[c * 132 + r + 8]        = A1.x;
            sD[(c + 1) * 132 + r + 8]  = A1.y;
            sD[c * 132 + r + 16]       = B0.x;
            sD[(c + 1) * 132 + r + 16] = B0.y;
            sD[c * 132 + r + 24]       = B1.x;
            sD[(c + 1) * 132 + r + 24] = B1.y;
        }
    }
    __syncthreads();

    // ---- po stores as f16 (uint2 = 4 halves) ----
#pragma unroll
    for (int k = 0; k < 16; k++) {
        const int flat = tid + 128 * k;
        const int c = flat >> 5, seg = flat & 31;
        const float4 v = *(const float4*)&sD[c * 132 + seg * 4];
        uint2 h;
        h.x = cvtf16x2(v.x, v.y);
        h.y = cvtf16x2(v.z, v.w);
        *(uint2*)&g_po[(((size_t)(b * KS + s) * Cc + c)) * Nn + row0 + seg * 4] = h;
    }
}

// ============================================================
// Kernel 3: merge 4 f16 splits + gamma residual (fully parallel)
// ============================================================
__global__ void __launch_bounds__(256) reduce_kernel(
    const float* __restrict__ x,
    const float* __restrict__ gamma,
    float* __restrict__ out)
{
    const int i = blockIdx.x * 256 + threadIdx.x;
    const size_t flat = (size_t)i * 4;
    const int b = (int)(flat / ((size_t)Cc * Nn));
    const int rem = (int)(flat - (size_t)b * Cc * Nn);
    const int c = rem / Nn;
    const int n = rem % Nn;

    float4 os = make_float4(0.f, 0.f, 0.f, 0.f);
    float4 ls = make_float4(0.f, 0.f, 0.f, 0.f);
#pragma unroll
    for (int s = 0; s < KS; s++) {
        const uint2 oh = *(const uint2*)&g_po[(((size_t)(b * KS + s) * Cc + c)) * Nn + n];
        const float2 o01 = __half22float2(*(const __half2*)&oh.x);
        const float2 o23 = __half22float2(*(const __half2*)&oh.y);
        const float4 l = *(const float4*)&g_pl[((size_t)(b * KS + s)) * Nn + n];
        os.x += o01.x; os.y += o01.y; os.z += o23.x; os.w += o23.y;
        ls.x += l.x; ls.y += l.y; ls.z += l.z; ls.w += l.w;
    }
    const float4 xv = *(const float4*)&x[flat];
    const float gm = __ldg(gamma);

    float4 r;
    r.x = fmaf(gm, os.x / ls.x, xv.x);
    r.y = fmaf(gm, os.y / ls.y, xv.y);
    r.z = fmaf(gm, os.z / ls.z, xv.z);
    r.w = fmaf(gm, os.w / ls.w, xv.w);
    *(float4*)&out[flat] = r;
}

// ============================================================
extern "C" void kernel_launch(void* const* d_in, const int* in_sizes, int n_in,
                              void* d_out, int out_size)
{
    const float* x     = (const float*)d_in[0];
    const float* Wq    = (const float*)d_in[1];
    const float* bq    = (const float*)d_in[2];
    const float* Wk    = (const float*)d_in[3];
    const float* bk    = (const float*)d_in[4];
    const float* Wv    = (const float*)d_in[5];
    const float* bv    = (const float*)d_in[6];
    const float* gamma = (const float*)d_in[7];
    float* out = (float*)d_out;

    dim3 g1(Nn / 128, Bb);
    qkv_kernel<<<g1, 256>>>(x, Wq, bq, Wk, bk, Wv, bv);

    dim3 g2(Nn / NQ, KS, Bb);
    attn_kernel<<<g2, 128>>>();

    reduce_kernel<<<(Bb * Cc * Nn / 4) / 256, 256>>>(x, gamma, out);
}

// round 16
// speedup vs baseline: 1.0779x; 1.0779x over previous
#include <cuda_runtime.h>
#include <cuda_fp16.h>
#include <cstdint>

// Problem constants
#define Bb 4
#define Cc 64
#define Dd 8
#define Nn 4096          // H*W
#define LOG2E 1.4426950408889634f
#define TK 128           // keys per tile
#define NQ 128           // queries per CTA
#define KS 4             // key splits
#define NTS (Nn / TK / KS)   // 8 tiles per CTA

// Scratch (allocation-free rule: __device__ globals) — all row-major [row][n] f16
__device__ __half g_qh[Bb * Dd * Nn];                // [b][d][n] f16 (q, scaled by log2e)
__device__ __half g_kh[Bb * Dd * Nn];                // [b][d][n] f16
__device__ __half g_vh[Bb * Cc * Nn];                // [b][c][n] f16
__device__ __half g_po[Bb * KS * Cc * Nn];           // partial O (unnormalized, f16)
__device__ float  g_pl[Bb * KS * Nn];                // partial l

// ---------------- PTX helpers (baseline ISA only) ----------------
__device__ __forceinline__ uint32_t smem_u32(const void* p) {
    uint32_t a;
    asm("{ .reg .u64 t; cvta.to.shared.u64 t, %1; cvt.u32.u64 %0, t; }" : "=r"(a) : "l"(p));
    return a;
}
// d = {lo, hi} f16x2 (lo in low half)
__device__ __forceinline__ uint32_t cvtf16x2(float lo, float hi) {
    uint32_t r;
    asm("cvt.rn.f16x2.f32 %0, %1, %2;" : "=r"(r) : "f"(hi), "f"(lo));
    return r;
}
__device__ __forceinline__ uint32_t ex2h2(uint32_t a) {
    uint32_t r;
    asm("ex2.approx.f16x2 %0, %1;" : "=r"(r) : "r"(a));
    return r;
}
__device__ __forceinline__ void ldsm4(uint32_t& r0, uint32_t& r1, uint32_t& r2,
                                      uint32_t& r3, uint32_t a) {
    asm volatile("ldmatrix.sync.aligned.m8n8.x4.shared.b16 {%0, %1, %2, %3}, [%4];"
                 : "=r"(r0), "=r"(r1), "=r"(r2), "=r"(r3) : "r"(a));
}
__device__ __forceinline__ void ldsm2t(uint32_t& r0, uint32_t& r1, uint32_t a) {
    asm volatile("ldmatrix.sync.aligned.m8n8.x2.trans.shared.b16 {%0, %1}, [%2];"
                 : "=r"(r0), "=r"(r1) : "r"(a));
}
__device__ __forceinline__ void sts32(uint32_t a, uint32_t v) {
    asm volatile("st.shared.b32 [%0], %1;" :: "r"(a), "r"(v) : "memory");
}
__device__ __forceinline__ void sts_v2b32(uint32_t a, uint32_t x, uint32_t y) {
    asm volatile("st.shared.v2.b32 [%0], {%1, %2};" :: "r"(a), "r"(x), "r"(y) : "memory");
}
__device__ __forceinline__ void lds128(uint32_t a, uint32_t& x, uint32_t& y,
                                       uint32_t& z, uint32_t& w) {
    asm volatile("ld.shared.v4.b32 {%0, %1, %2, %3}, [%4];"
                 : "=r"(x), "=r"(y), "=r"(z), "=r"(w) : "r"(a));
}
__device__ __forceinline__ void cp16(uint32_t dst, const void* src) {
    asm volatile("cp.async.ca.shared.global [%0], [%1], 16;" :: "r"(dst), "l"(src) : "memory");
}
#define CP_COMMIT() asm volatile("cp.async.commit_group;" ::: "memory")
#define CP_WAIT1()  asm volatile("cp.async.wait_group 1;" ::: "memory")
#define CP_WAIT0()  asm volatile("cp.async.wait_group 0;" ::: "memory")

// S[16q x 8k] = Q[16x8] * K^T, f16 accumulate from zero -> packed f16x2 D
__device__ __forceinline__ void mma_qk8h(uint32_t d[2], uint32_t a0, uint32_t a1,
                                         uint32_t b0) {
    const uint32_t Z = 0;
    asm volatile(
        "mma.sync.aligned.m16n8k8.row.col.f16.f16.f16.f16 "
        "{%0,%1}, {%2,%3}, {%4}, {%5,%5};"
        : "=r"(d[0]), "=r"(d[1])
        : "r"(a0), "r"(a1), "r"(b0), "r"(Z));
}
__device__ __forceinline__ void mma16816(float d[4], uint32_t a0, uint32_t a1,
                                         uint32_t a2, uint32_t a3,
                                         uint32_t b0, uint32_t b1) {
    asm volatile(
        "mma.sync.aligned.m16n8k16.row.col.f32.f16.f16.f32 "
        "{%0,%1,%2,%3}, {%4,%5,%6,%7}, {%8,%9}, {%0,%1,%2,%3};"
        : "+f"(d[0]), "+f"(d[1]), "+f"(d[2]), "+f"(d[3])
        : "r"(a0), "r"(a1), "r"(a2), "r"(a3), "r"(b0), "r"(b1));
}
__device__ __forceinline__ void ldsm4t(uint32_t& r0, uint32_t& r1, uint32_t& r2,
                                       uint32_t& r3, uint32_t a) {
    asm volatile("ldmatrix.sync.aligned.m8n8.x4.trans.shared.b16 {%0, %1, %2, %3}, [%4];"
                 : "=r"(r0), "=r"(r1), "=r"(r2), "=r"(r3) : "r"(a));
}

// ============================================================
// Kernel 1: fused 1x1-conv QKV projection on HMMA.
//   512 threads = 16 warps; warp w owns pixel strip w*8..w*8+7.
//   A = stacked [Wv;Wq*log2e;Wk] (80x64 f16, 144B rows)
//   B = x tile ([64c][128px] f16, 272B rows), ldsm.x2.trans per ks.
//   Per warp: 4ks x 5rt mma.16816 -> [80 o][8 px].
// grid (Nn/128, Bb)
// ============================================================
__global__ void __launch_bounds__(512) qkv_kernel(
    const float* __restrict__ x,
    const float* __restrict__ Wq, const float* __restrict__ bq,
    const float* __restrict__ Wk, const float* __restrict__ bk,
    const float* __restrict__ Wv, const float* __restrict__ bv)
{
    __shared__ __align__(16) char smem[28928];   // WH 11520 | XH 17408 ; TR reuses [0,21760)
    const uint32_t sb = smem_u32(smem);
    const uint32_t WH = sb;
    const uint32_t XH = sb + 11520;
    const uint32_t TR = sb;

    const int tid  = threadIdx.x;
    const int w    = tid >> 5;
    const int lane = tid & 31;
    const int gid  = lane >> 2;
    const int tg   = lane & 3;
    const int b    = blockIdx.y;
    const int n0   = blockIdx.x * 128;

    // ---- convert stacked W -> f16 smem (rows 144B): 2560 f16x2 ----
#pragma unroll
    for (int i = 0; i < 5; i++) {
        const int flat = (tid + i * 512) * 2;      // even f32 index in 80x64
        const int o = flat >> 6, c = flat & 63;
        const float* src = (o < 64) ? Wv + o * 64 + c
                         : (o < 72) ? Wq + (o - 64) * 64 + c
                                    : Wk + (o - 72) * 64 + c;
        const float2 v = *(const float2*)src;
        const float scl = (o >= 64 && o < 72) ? LOG2E : 1.0f;
        sts32(WH + (uint32_t)(o * 144 + c * 2), cvtf16x2(v.x * scl, v.y * scl));
    }
    // ---- convert x tile -> f16 smem [c][px] (rows 272B): 2048 chunks ----
#pragma unroll
    for (int i = 0; i < 4; i++) {
        const int id = tid + i * 512;
        const int c = id >> 5, ch = id & 31;
        const float4 v = *(const float4*)&x[(size_t)(b * Cc + c) * Nn + n0 + ch * 4];
        sts_v2b32(XH + (uint32_t)(c * 272 + ch * 8),
                  cvtf16x2(v.x, v.y), cvtf16x2(v.z, v.w));
    }
    // ---- per-thread biases (rt<4: V rows; rt=4: Q(gid)/K(gid)) ----
    float bias[5][2];
#pragma unroll
    for (int rt = 0; rt < 4; rt++) {
        bias[rt][0] = bv[rt * 16 + gid];
        bias[rt][1] = bv[rt * 16 + gid + 8];
    }
    bias[4][0] = bq[gid] * LOG2E;
    bias[4][1] = bk[gid];

    __syncthreads();

    // ---- GEMM: each warp 80 o x 8 px ----
    float acc[5][4];
#pragma unroll
    for (int rt = 0; rt < 5; rt++)
#pragma unroll
        for (int i = 0; i < 4; i++) acc[rt][i] = 0.f;

    const int wpx = w * 8;
    const uint32_t aoff = WH + (uint32_t)((lane & 15) * 144 + (lane >> 4) * 16);
    const uint32_t boff = XH + (uint32_t)((lane & 15) * 272 + wpx * 2);
#pragma unroll
    for (int ks = 0; ks < 4; ks++) {
        uint32_t b0, b1;
        ldsm2t(b0, b1, boff + (uint32_t)(ks * 16 * 272));
#pragma unroll
        for (int rt = 0; rt < 5; rt++) {
            uint32_t a0, a1, a2, a3;
            ldsm4(a0, a1, a2, a3, aoff + (uint32_t)(rt * 16 * 144 + ks * 32));
            mma16816(acc[rt], a0, a1, a2, a3, b0, b1);
        }
    }
    __syncthreads();

    // ---- transpose tile [o][px] f16 (rows 272B) ----
#pragma unroll
    for (int rt = 0; rt < 5; rt++) {
        const int px = wpx + tg * 2;
        const int o0 = rt * 16 + gid;
        sts32(TR + (uint32_t)(o0 * 272 + px * 2),
              cvtf16x2(acc[rt][0] + bias[rt][0], acc[rt][1] + bias[rt][0]));
        sts32(TR + (uint32_t)((o0 + 8) * 272 + px * 2),
              cvtf16x2(acc[rt][2] + bias[rt][1], acc[rt][3] + bias[rt][1]));
    }
    __syncthreads();

    // ---- coalesced stores: V 1024 chunks, Q/K 256 chunks ----
#pragma unroll
    for (int i = 0; i < 2; i++) {
        const int id = tid + i * 512;
        const int o = id >> 4, kc = id & 15;
        uint32_t v0, v1, v2, v3;
        lds128(TR + (uint32_t)(o * 272 + kc * 16), v0, v1, v2, v3);
        uint4* dst = (uint4*)&g_vh[(size_t)(b * Cc + o) * Nn + n0 + kc * 8];
        *dst = make_uint4(v0, v1, v2, v3);
    }
    if (tid < 256) {
        const int d16 = tid >> 4, kc = tid & 15;
        uint32_t v0, v1, v2, v3;
        lds128(TR + (uint32_t)((64 + d16) * 272 + kc * 16), v0, v1, v2, v3);
        __half* base = (d16 < 8) ? &g_qh[(size_t)(b * Dd + d16) * Nn]
                                 : &g_kh[(size_t)(b * Dd + d16 - 8) * Nn];
        *(uint4*)&base[n0 + kc * 8] = make_uint4(v0, v1, v2, v3);
    }
}

// ============================================================
// Kernel 2: attention — round-14 version (f32-accum PV).
//   128 threads / 4 warps, 32 queries per warp.
//   QK f16-accum mma; exp f16x2; PV f32-accum mma; l f32-accum mma.
//   Partial O stored f16. grid (32, KS=4, Bb) = 512 CTAs.
// ============================================================
__global__ void __launch_bounds__(128) attn_kernel()
{
    // 2 bufs x (2176B K + 17408B V) = 39168; epilogue sD 64x132 f32 = 33792
    __shared__ __align__(16) char smem[39168];
    const uint32_t sb = smem_u32(smem);

    const int tid  = threadIdx.x;
    const int w    = tid >> 5;
    const int lane = tid & 31;
    const int gid  = lane >> 2;   // 0..7
    const int tg   = lane & 3;    // 0..3
    const int b    = blockIdx.z;
    const int s    = blockIdx.y;
    const int row0 = blockIdx.x * NQ;
    const int key0 = s * (Nn / KS);
    const int rbase = row0 + w * 32 + gid;

    // ---- Q A-frags for two 16-row sets ----
    uint32_t qA0, qA1, qB0, qB1;
    {
        const size_t qb = (size_t)b * Dd * Nn;
        const __half* q0 = &g_qh[qb + (size_t)(2 * tg) * Nn];
        const __half* q1 = &g_qh[qb + (size_t)(2 * tg + 1) * Nn];
        qA0 = (uint32_t)*(const unsigned short*)&q0[rbase]
            | ((uint32_t)*(const unsigned short*)&q1[rbase] << 16);
        qA1 = (uint32_t)*(const unsigned short*)&q0[rbase + 8]
            | ((uint32_t)*(const unsigned short*)&q1[rbase + 8] << 16);
        qB0 = (uint32_t)*(const unsigned short*)&q0[rbase + 16]
            | ((uint32_t)*(const unsigned short*)&q1[rbase + 16] << 16);
        qB1 = (uint32_t)*(const unsigned short*)&q0[rbase + 24]
            | ((uint32_t)*(const unsigned short*)&q1[rbase + 24] << 16);
    }

    // ---- loop-constant ldmatrix lane offsets ----
    const int l16 = lane & 15;
    const uint32_t kmoff = (uint32_t)((l16 & 7) * 272 + (l16 >> 3) * 16);
    const int q2 = lane >> 3;
    uint32_t vmoff[4];
#pragma unroll
    for (int g = 0; g < 4; g++)
        vmoff[g] = (uint32_t)((g * 16 + (q2 >> 1) * 8 + (lane & 7)) * 272
                              + (q2 & 1) * 16);

    float dacA[8][4], dacB[8][4];
#pragma unroll
    for (int nt = 0; nt < 8; nt++)
#pragma unroll
        for (int i = 0; i < 4; i++) { dacA[nt][i] = 0.f; dacB[nt][i] = 0.f; }
    float dlA[4] = {0.f, 0.f, 0.f, 0.f};
    float dlB[4] = {0.f, 0.f, 0.f, 0.f};
    const uint32_t ONES = 0x3C003C00u;

    auto prefetch = [&](int t, int buf) {
        const uint32_t kdst = sb + (uint32_t)buf * 19584u;
        const uint32_t vdst = kdst + 2176u;
        {
            const int d = tid >> 4, kc = tid & 15;
            cp16(kdst + (uint32_t)(d * 272 + kc * 16),
                 &g_kh[(size_t)(b * Dd + d) * Nn + key0 + t * TK + kc * 8]);
        }
#pragma unroll
        for (int j = 0; j < 8; j++) {
            const int id = tid + 128 * j;
            const int c = id >> 4, kc = id & 15;
            cp16(vdst + (uint32_t)(c * 272 + kc * 16),
                 &g_vh[(size_t)(b * Cc + c) * Nn + key0 + t * TK + kc * 8]);
        }
    };

    prefetch(0, 0);
    CP_COMMIT();

#pragma unroll 1
    for (int t = 0; t < NTS; t++) {
        if (t + 1 < NTS) { prefetch(t + 1, (t + 1) & 1); CP_COMMIT(); CP_WAIT1(); }
        else             { CP_WAIT0(); }
        __syncthreads();

        const uint32_t Kb = sb + (uint32_t)(t & 1) * 19584u;
        const uint32_t Vb = Kb + 2176u;

#pragma unroll
        for (int ks = 0; ks < 8; ks++) {
            uint32_t kb0, kb1;
            ldsm2t(kb0, kb1, Kb + (uint32_t)(ks * 32) + kmoff);
            // f16-accum QK: D regs are packed f16x2 in PV A-frag layout
            uint32_t sA0[2], sA1[2], sB0[2], sB1[2];
            mma_qk8h(sA0, qA0, qA1, kb0);
            mma_qk8h(sA1, qA0, qA1, kb1);
            mma_qk8h(sB0, qB0, qB1, kb0);
            mma_qk8h(sB1, qB0, qB1, kb1);

            const uint32_t a0 = ex2h2(sA0[0]);
            const uint32_t a1 = ex2h2(sA0[1]);
            const uint32_t a2 = ex2h2(sA1[0]);
            const uint32_t a3 = ex2h2(sA1[1]);
            const uint32_t a4 = ex2h2(sB0[0]);
            const uint32_t a5 = ex2h2(sB0[1]);
            const uint32_t a6 = ex2h2(sB1[0]);
            const uint32_t a7 = ex2h2(sB1[1]);

            const uint32_t vstep = Vb + (uint32_t)(ks * 32);
#pragma unroll
            for (int g = 0; g < 4; g++) {
                uint32_t r0, r1, r2, r3;
                ldsm4(r0, r1, r2, r3, vstep + vmoff[g]);
                mma16816(dacA[2 * g],     a0, a1, a2, a3, r0, r1);
                mma16816(dacB[2 * g],     a4, a5, a6, a7, r0, r1);
                mma16816(dacA[2 * g + 1], a0, a1, a2, a3, r2, r3);
                mma16816(dacB[2 * g + 1], a4, a5, a6, a7, r2, r3);
            }
            mma16816(dlA, a0, a1, a2, a3, ONES, ONES);
            mma16816(dlB, a4, a5, a6, a7, ONES, ONES);
        }
        __syncthreads();
    }

    // ---- partial l (rows rbase+{0,8,16,24}) ----
    if (tg == 0) {
        const size_t lb = ((size_t)(b * KS + s)) * Nn + rbase;
        g_pl[lb]      = dlA[0];
        g_pl[lb + 8]  = dlA[2];
        g_pl[lb + 16] = dlB[0];
        g_pl[lb + 24] = dlB[2];
    }

    // ---- transpose unnormalized O through smem (stride 132) ----
    float* sD = (float*)smem;
    {
        const int r = w * 32 + gid;
#pragma unroll
        for (int nt = 0; nt < 8; nt++) {
            const int c = nt * 8 + tg * 2;
            sD[c * 132 + r]            = dacA[nt][0];
            sD[(c + 1) * 132 + r]      = dacA[nt][1];
            sD[c * 132 + r + 8]        = dacA[nt][2];
            sD[(c + 1) * 132 + r + 8]  = dacA[nt][3];
            sD[c * 132 + r + 16]       = dacB[nt][0];
            sD[(c + 1) * 132 + r + 16] = dacB[nt][1];
            sD[c * 132 + r + 24]       = dacB[nt][2];
            sD[(c + 1) * 132 + r + 24] = dacB[nt][3];
        }
    }
    __syncthreads();

    // ---- po stores as f16 (uint2 = 4 halves) ----
#pragma unroll
    for (int k = 0; k < 16; k++) {
        const int flat = tid + 128 * k;
        const int c = flat >> 5, seg = flat & 31;
        const float4 v = *(const float4*)&sD[c * 132 + seg * 4];
        uint2 h;
        h.x = cvtf16x2(v.x, v.y);
        h.y = cvtf16x2(v.z, v.w);
        *(uint2*)&g_po[(((size_t)(b * KS + s) * Cc + c)) * Nn + row0 + seg * 4] = h;
    }
}

// ============================================================
// Kernel 3: merge 4 f16 splits + gamma residual (fully parallel)
// ============================================================
__global__ void __launch_bounds__(256) reduce_kernel(
    const float* __restrict__ x,
    const float* __restrict__ gamma,
    float* __restrict__ out)
{
    const int i = blockIdx.x * 256 + threadIdx.x;
    const size_t flat = (size_t)i * 4;
    const int b = (int)(flat / ((size_t)Cc * Nn));
    const int rem = (int)(flat - (size_t)b * Cc * Nn);
    const int c = rem / Nn;
    const int n = rem % Nn;

    float4 os = make_float4(0.f, 0.f, 0.f, 0.f);
    float4 ls = make_float4(0.f, 0.f, 0.f, 0.f);
#pragma unroll
    for (int s = 0; s < KS; s++) {
        const uint2 oh = *(const uint2*)&g_po[(((size_t)(b * KS + s) * Cc + c)) * Nn + n];
        const float2 o01 = __half22float2(*(const __half2*)&oh.x);
        const float2 o23 = __half22float2(*(const __half2*)&oh.y);
        const float4 l = *(const float4*)&g_pl[((size_t)(b * KS + s)) * Nn + n];
        os.x += o01.x; os.y += o01.y; os.z += o23.x; os.w += o23.y;
        ls.x += l.x; ls.y += l.y; ls.z += l.z; ls.w += l.w;
    }
    const float4 xv = *(const float4*)&x[flat];
    const float gm = __ldg(gamma);

    float4 r;
    r.x = fmaf(gm, os.x / ls.x, xv.x);
    r.y = fmaf(gm, os.y / ls.y, xv.y);
    r.z = fmaf(gm, os.z / ls.z, xv.z);
    r.w = fmaf(gm, os.w / ls.w, xv.w);
    *(float4*)&out[flat] = r;
}

// ============================================================
extern "C" void kernel_launch(void* const* d_in, const int* in_sizes, int n_in,
                              void* d_out, int out_size)
{
    const float* x     = (const float*)d_in[0];
    const float* Wq    = (const float*)d_in[1];
    const float* bq    = (const float*)d_in[2];
    const float* Wk    = (const float*)d_in[3];
    const float* bk    = (const float*)d_in[4];
    const float* Wv    = (const float*)d_in[5];
    const float* bv    = (const float*)d_in[6];
    const float* gamma = (const float*)d_in[7];
    float* out = (float*)d_out;

    dim3 g1(Nn / 128, Bb);
    qkv_kernel<<<g1, 512>>>(x, Wq, bq, Wk, bk, Wv, bv);

    dim3 g2(Nn / NQ, KS, Bb);
    attn_kernel<<<g2, 128>>>();

    reduce_kernel<<<(Bb * Cc * Nn / 4) / 256, 256>>>(x, gamma, out);
}